// round 7
// baseline (speedup 1.0000x reference)
#include <cuda_runtime.h>
#include <cuda_fp16.h>
#include <cstdint>

// Problem constants: B=2, T=8192, D=2048, W=128
#define BATCH 2
#define SEQ   8192
#define DIM   2048
#define WIN   128
#define NBLK  64
#define ROWS  16384
#define QKVN  6144

// Scratch (device globals: the sanctioned alloc-free workaround)
__device__ __half g_qkv[(size_t)ROWS * QKVN];
__device__ float  g_attn[(size_t)BATCH * NBLK * 128 * 256];
__device__ __half g_ao[(size_t)ROWS * DIM];
__device__ __half g_xh[(size_t)ROWS * DIM];
__device__ __half g_wah[(size_t)QKVN * DIM];
__device__ __half g_woh[(size_t)DIM * DIM];

// ---------------------------------------------------------------------------
// helpers
// ---------------------------------------------------------------------------
__device__ __forceinline__ uint32_t smem_u32(const void* p) {
    uint32_t a;
    asm("{ .reg .u64 t; cvta.to.shared.u64 t, %1; cvt.u32.u64 %0, t; }" : "=r"(a) : "l"(p));
    return a;
}
__device__ __forceinline__ float cvt_tf32(float x) {
    uint32_t u;
    asm("cvt.rna.tf32.f32 %0, %1;" : "=r"(u) : "f"(x));
    return __uint_as_float(u);
}

__device__ __forceinline__ void mma_f16(float& d0, float& d1, float& d2, float& d3,
                                        uint32_t a0, uint32_t a1, uint32_t a2, uint32_t a3,
                                        uint32_t b0, uint32_t b1) {
    asm volatile(
        "mma.sync.aligned.m16n8k16.row.col.f32.f16.f16.f32 "
        "{%0,%1,%2,%3}, {%4,%5,%6,%7}, {%8,%9}, {%0,%1,%2,%3};\n"
        : "+f"(d0), "+f"(d1), "+f"(d2), "+f"(d3)
        : "r"(a0), "r"(a1), "r"(a2), "r"(a3), "r"(b0), "r"(b1));
}
__device__ __forceinline__ void mma_tf32(float& d0, float& d1, float& d2, float& d3,
                                         float a0, float a1, float a2, float a3,
                                         float b0, float b1) {
    asm volatile(
        "mma.sync.aligned.m16n8k8.row.col.f32.tf32.tf32.f32 "
        "{%0,%1,%2,%3}, {%4,%5,%6,%7}, {%8,%9}, {%0,%1,%2,%3};\n"
        : "+f"(d0), "+f"(d1), "+f"(d2), "+f"(d3)
        : "r"(__float_as_uint(a0)), "r"(__float_as_uint(a1)),
          "r"(__float_as_uint(a2)), "r"(__float_as_uint(a3)),
          "r"(__float_as_uint(b0)), "r"(__float_as_uint(b1)));
}

#define LDSM_X4(r0, r1, r2, r3, addr)                                          \
    asm volatile("ldmatrix.sync.aligned.m8n8.x4.shared.b16 {%0,%1,%2,%3}, [%4];" \
                 : "=r"(r0), "=r"(r1), "=r"(r2), "=r"(r3) : "r"(addr))

#define CP_ASYNC16(dst, src)                                                   \
    asm volatile("cp.async.cg.shared.global [%0], [%1], 16;"                   \
                 :: "r"(dst), "l"(src) : "memory")
#define CP_COMMIT() asm volatile("cp.async.commit_group;" ::: "memory")
#define CP_WAIT1()  asm volatile("cp.async.wait_group 1;" ::: "memory")

// ---------------------------------------------------------------------------
// BIG GEMM geometry: CTA tile 128(M) x 256(N), K-tile 64 halves.
// Row = 64 halves + 8 pad = 144B. A: 128x144, B: 256x144 per stage.
#define ROW_B     144
#define GA_MAT_A  18432                 // A bytes per stage (128*144)
#define GA_STAGE  55296                 // (128+256)*144
#define GA_NSTAGE 3
#define GA_SMEM   (GA_NSTAGE * GA_STAGE)   // 165888 <= 227KB (1 CTA/SM)

// sim geometry (unchanged from round 6): 128x128 tile
#define SI_MAT_B  18432
#define SI_STAGE  36864
#define SI_SMEM   (3 * SI_STAGE)

// ---------------------------------------------------------------------------
// fp16 NT GEMM: C[M,N] = A[M,K] @ B[N,K]^T, CTA 128x256, warp tile 64x64,
// 8 warps (2M x 4N), 3-stage cp.async, 1 CTA/SM.
// ---------------------------------------------------------------------------
__global__ __launch_bounds__(256, 1)
void gemm_h_kernel(const __half* __restrict__ A, const __half* __restrict__ B,
                   void* __restrict__ Cout, int lda, int ldb, int N, int K,
                   int out_half) {
    extern __shared__ __align__(128) char smem[];
    const uint32_t smem_base = smem_u32(smem);

    const int tid  = threadIdx.x;
    const int warp = tid >> 5, lane = tid & 31;
    const int wm = (warp & 1) << 6;    // 0, 64
    const int wn = (warp >> 1) << 6;   // 0, 64, 128, 192
    const int g  = lane >> 2, tg = lane & 3;
    const int lr = tid >> 3;           // copy row 0..31
    const int c4 = tid & 7;            // copy 16B chunk 0..7

    const int sel = lane >> 3;
    const int i8  = lane & 7;
    // A fragments: 4 tiles of 16 rows (wm + 16*mf), each LDSM.x4 = 16rows x 16k
    uint32_t a_addr[4], b_addr[4];
    #pragma unroll
    for (int mf = 0; mf < 4; mf++) {
        const int row = wm + 16 * mf + (sel & 1) * 8 + i8;
        a_addr[mf] = smem_base + (uint32_t)row * ROW_B + (sel >> 1) * 16;
    }
    // B fragments: 4 tiles of 16 N-rows (wn + 16*np)
    #pragma unroll
    for (int np = 0; np < 4; np++) {
        const int row = wn + np * 16 + (sel >> 1) * 8 + i8;
        b_addr[np] = smem_base + GA_MAT_A + (uint32_t)row * ROW_B + (sel & 1) * 16;
    }

    const __half* Ab = A + (size_t)(blockIdx.y * 128 + lr) * lda + c4 * 8;
    const __half* Bb = B + (size_t)(blockIdx.x * 256 + lr) * ldb + c4 * 8;
    const uint32_t dA = smem_base + (uint32_t)lr * ROW_B + c4 * 16;
    const uint32_t dB = smem_base + GA_MAT_A + (uint32_t)lr * ROW_B + c4 * 16;

    float acc[4][8][4];   // [mf][nf][q] = 128 regs
    #pragma unroll
    for (int i = 0; i < 4; i++)
        #pragma unroll
        for (int j = 0; j < 8; j++)
            #pragma unroll
            for (int q = 0; q < 4; q++) acc[i][j][q] = 0.f;

    const int NT = K >> 6;

    // prologue: stages 0, 1
    #pragma unroll
    for (int s = 0; s < 2; s++) {
        const uint32_t o = (uint32_t)s * GA_STAGE;
        const __half* An = Ab + s * 64;
        const __half* Bn = Bb + s * 64;
        #pragma unroll
        for (int j = 0; j < 4; j++)
            CP_ASYNC16(dA + o + j * (32 * ROW_B), An + (size_t)(j * 32) * lda);
        #pragma unroll
        for (int j = 0; j < 8; j++)
            CP_ASYNC16(dB + o + j * (32 * ROW_B), Bn + (size_t)(j * 32) * ldb);
        CP_COMMIT();
    }

    uint32_t af[4][4], bf[4][4];
    int s_cur = 0, s_nxt = 2;

    for (int it = 0; it < NT; it++) {
        CP_WAIT1();
        __syncthreads();

        if (it + 2 < NT) {
            const uint32_t o = (uint32_t)s_nxt * GA_STAGE;
            const __half* An = Ab + (it + 2) * 64;
            const __half* Bn = Bb + (it + 2) * 64;
            #pragma unroll
            for (int j = 0; j < 4; j++)
                CP_ASYNC16(dA + o + j * (32 * ROW_B), An + (size_t)(j * 32) * lda);
            #pragma unroll
            for (int j = 0; j < 8; j++)
                CP_ASYNC16(dB + o + j * (32 * ROW_B), Bn + (size_t)(j * 32) * ldb);
        }
        CP_COMMIT();

        const uint32_t so = (uint32_t)s_cur * GA_STAGE;
        #pragma unroll
        for (int ks = 0; ks < 4; ks++) {           // 4 x k16
            const uint32_t ko = so + (uint32_t)ks * 32;
            #pragma unroll
            for (int mf = 0; mf < 4; mf++)
                LDSM_X4(af[mf][0], af[mf][1], af[mf][2], af[mf][3], a_addr[mf] + ko);
            #pragma unroll
            for (int np = 0; np < 4; np++)
                LDSM_X4(bf[np][0], bf[np][1], bf[np][2], bf[np][3], b_addr[np] + ko);
            #pragma unroll
            for (int mf = 0; mf < 4; mf++)
                #pragma unroll
                for (int np = 0; np < 4; np++) {
                    mma_f16(acc[mf][2 * np + 0][0], acc[mf][2 * np + 0][1],
                            acc[mf][2 * np + 0][2], acc[mf][2 * np + 0][3],
                            af[mf][0], af[mf][1], af[mf][2], af[mf][3],
                            bf[np][0], bf[np][1]);
                    mma_f16(acc[mf][2 * np + 1][0], acc[mf][2 * np + 1][1],
                            acc[mf][2 * np + 1][2], acc[mf][2 * np + 1][3],
                            af[mf][0], af[mf][1], af[mf][2], af[mf][3],
                            bf[np][2], bf[np][3]);
                }
        }
        s_cur = (s_cur == 2) ? 0 : s_cur + 1;
        s_nxt = (s_nxt == 2) ? 0 : s_nxt + 1;
    }

    #pragma unroll
    for (int mf = 0; mf < 4; mf++) {
        #pragma unroll
        for (int nf = 0; nf < 8; nf++) {
            const int row = blockIdx.y * 128 + wm + mf * 16 + g;
            const int col = blockIdx.x * 256 + wn + nf * 8 + (tg << 1);
            if (out_half) {
                __half* C = (__half*)Cout;
                *(__half2*)(C + (size_t)row * N + col) =
                    __floats2half2_rn(acc[mf][nf][0], acc[mf][nf][1]);
                *(__half2*)(C + (size_t)(row + 8) * N + col) =
                    __floats2half2_rn(acc[mf][nf][2], acc[mf][nf][3]);
            } else {
                float* C = (float*)Cout;
                *(float2*)(C + (size_t)row * N + col) =
                    make_float2(acc[mf][nf][0], acc[mf][nf][1]);
                *(float2*)(C + (size_t)(row + 8) * N + col) =
                    make_float2(acc[mf][nf][2], acc[mf][nf][3]);
            }
        }
    }
}

// ---------------------------------------------------------------------------
// sim kernel (fp16, unchanged from round 6): 128x128 QK^T, mask+1/W+relu^2.
// ---------------------------------------------------------------------------
__global__ __launch_bounds__(256, 2)
void attn_sim_kernel(const __half* __restrict__ qkv, float* __restrict__ attnOut) {
    extern __shared__ __align__(128) char smem[];
    const uint32_t smem_base = smem_u32(smem);
    const int half_ = blockIdx.x, w = blockIdx.y, b = blockIdx.z;

    const int tid  = threadIdx.x;
    const int warp = tid >> 5, lane = tid & 31;
    const int wm = (warp & 3) << 5;
    const int wn = (warp >> 2) << 6;
    const int g  = lane >> 2, tg = lane & 3;
    const int lr = tid >> 3;
    const int c4 = tid & 7;

    const int sel = lane >> 3;
    const int i8  = lane & 7;
    uint32_t a_addr[2], b_addr[4];
    #pragma unroll
    for (int mf = 0; mf < 2; mf++) {
        const int row = wm + 16 * mf + (sel & 1) * 8 + i8;
        a_addr[mf] = smem_base + (uint32_t)row * ROW_B + (sel >> 1) * 16;
    }
    #pragma unroll
    for (int np = 0; np < 4; np++) {
        const int row = wn + np * 16 + (sel >> 1) * 8 + i8;
        b_addr[np] = smem_base + SI_MAT_B + (uint32_t)row * ROW_B + (sel & 1) * 16;
    }

    const int kblk = (half_ == 0) ? (w > 0 ? w - 1 : 0) : w;
    const __half* Ab = qkv + (size_t)(b * SEQ + w * 128 + lr) * QKVN + c4 * 8;
    const __half* Bb = qkv + (size_t)(b * SEQ + kblk * 128 + lr) * QKVN + 2048 + c4 * 8;
    const uint32_t dA = smem_base + (uint32_t)lr * ROW_B + c4 * 16;
    const uint32_t dB = smem_base + SI_MAT_B + (uint32_t)lr * ROW_B + c4 * 16;

    float acc[2][8][4];
    #pragma unroll
    for (int i = 0; i < 2; i++)
        #pragma unroll
        for (int j = 0; j < 8; j++)
            #pragma unroll
            for (int q = 0; q < 4; q++) acc[i][j][q] = 0.f;

    const int NT = DIM >> 6;

    #pragma unroll
    for (int s = 0; s < 2; s++) {
        const uint32_t o = (uint32_t)s * SI_STAGE;
        const __half* An = Ab + s * 64;
        const __half* Bn = Bb + s * 64;
        #pragma unroll
        for (int j = 0; j < 4; j++) {
            CP_ASYNC16(dA + o + j * (32 * ROW_B), An + (size_t)(j * 32) * QKVN);
            CP_ASYNC16(dB + o + j * (32 * ROW_B), Bn + (size_t)(j * 32) * QKVN);
        }
        CP_COMMIT();
    }

    uint32_t af[2][4], bf[4][4];
    int s_cur = 0, s_nxt = 2;

    for (int it = 0; it < NT; it++) {
        CP_WAIT1();
        __syncthreads();

        if (it + 2 < NT) {
            const uint32_t o = (uint32_t)s_nxt * SI_STAGE;
            const __half* An = Ab + (it + 2) * 64;
            const __half* Bn = Bb + (it + 2) * 64;
            #pragma unroll
            for (int j = 0; j < 4; j++) {
                CP_ASYNC16(dA + o + j * (32 * ROW_B), An + (size_t)(j * 32) * QKVN);
                CP_ASYNC16(dB + o + j * (32 * ROW_B), Bn + (size_t)(j * 32) * QKVN);
            }
        }
        CP_COMMIT();

        const uint32_t so = (uint32_t)s_cur * SI_STAGE;
        #pragma unroll
        for (int ks = 0; ks < 4; ks++) {
            const uint32_t ko = so + (uint32_t)ks * 32;
            #pragma unroll
            for (int mf = 0; mf < 2; mf++)
                LDSM_X4(af[mf][0], af[mf][1], af[mf][2], af[mf][3], a_addr[mf] + ko);
            #pragma unroll
            for (int np = 0; np < 4; np++)
                LDSM_X4(bf[np][0], bf[np][1], bf[np][2], bf[np][3], b_addr[np] + ko);
            #pragma unroll
            for (int mf = 0; mf < 2; mf++)
                #pragma unroll
                for (int np = 0; np < 4; np++) {
                    mma_f16(acc[mf][2 * np + 0][0], acc[mf][2 * np + 0][1],
                            acc[mf][2 * np + 0][2], acc[mf][2 * np + 0][3],
                            af[mf][0], af[mf][1], af[mf][2], af[mf][3],
                            bf[np][0], bf[np][1]);
                    mma_f16(acc[mf][2 * np + 1][0], acc[mf][2 * np + 1][1],
                            acc[mf][2 * np + 1][2], acc[mf][2 * np + 1][3],
                            af[mf][0], af[mf][1], af[mf][2], af[mf][3],
                            bf[np][2], bf[np][3]);
                }
        }
        s_cur = (s_cur == 2) ? 0 : s_cur + 1;
        s_nxt = (s_nxt == 2) ? 0 : s_nxt + 1;
    }

    const bool halfvalid = (half_ == 1) || (w > 0);
    const float inv_w = 1.0f / (float)WIN;
    float* Cb = attnOut + ((size_t)(b * NBLK + w) * 128) * 256 + half_ * 128;

    #pragma unroll
    for (int mf = 0; mf < 2; mf++) {
        #pragma unroll
        for (int nf = 0; nf < 8; nf++) {
            const int qi0 = wm + mf * 16 + g;
            const int kj  = wn + nf * 8 + (tg << 1);
            #pragma unroll
            for (int rr = 0; rr < 2; rr++) {
                const int qi = qi0 + rr * 8;
                float s0 = acc[mf][nf][rr * 2 + 0] * inv_w;
                float s1 = acc[mf][nf][rr * 2 + 1] * inv_w;
                bool k0 = halfvalid && ((half_ == 0) ? (qi <= kj)     : (qi >= kj));
                bool k1 = halfvalid && ((half_ == 0) ? (qi <= kj + 1) : (qi >= kj + 1));
                float r0 = k0 ? fmaxf(s0, 0.f) : 0.f;
                float r1 = k1 ? fmaxf(s1, 0.f) : 0.f;
                float2 v;
                v.x = cvt_tf32(r0 * r0);
                v.y = cvt_tf32(r1 * r1);
                *(float2*)(Cb + (size_t)qi * 256 + kj) = v;
            }
        }
    }
}

// ---------------------------------------------------------------------------
// PV kernel (unchanged): attn(f32) @ V2(fp16->f32), tf32 mma, ao fp16 out.
// ---------------------------------------------------------------------------
__global__ __launch_bounds__(256, 1)
void attn_pv_kernel(const __half* __restrict__ qkv, const float* __restrict__ attn,
                    __half* __restrict__ ao) {
    const int nb = blockIdx.x * 128, w = blockIdx.y, b = blockIdx.z;
    __shared__ float As[128][36];
    __shared__ float Bs[32][136];

    const int tid  = threadIdx.x;
    const int warp = tid >> 5, lane = tid & 31;
    const int wm = (warp & 3) << 5;
    const int wn = (warp >> 2) << 6;
    const int g  = lane >> 2, tg = lane & 3;
    const int lr = tid >> 3;
    const int lc = (tid & 7) << 2;

    const int prevblk = (w > 0) ? w - 1 : 0;
    const float* Ab = attn + ((size_t)(b * NBLK + w) * 128 + lr) * 256 + lc;

    float acc[2][8][4];
    #pragma unroll
    for (int i = 0; i < 2; i++)
        #pragma unroll
        for (int j = 0; j < 8; j++)
            #pragma unroll
            for (int q = 0; q < 4; q++) acc[i][j][q] = 0.f;

    float4 ra[4];
    __half2 rv[4][2];
    {
        #pragma unroll
        for (int i = 0; i < 4; i++)
            ra[i] = *(const float4*)(Ab + (size_t)(i * 32) * 256);
        const int jj = lr;
        const int vrow = (jj < 128) ? (b * SEQ + prevblk * 128 + jj)
                                    : (b * SEQ + w * 128 + jj - 128);
        const __half* vp = qkv + (size_t)vrow * QKVN + 4096 + nb + lc;
        #pragma unroll
        for (int i = 0; i < 4; i++) {
            rv[i][0] = *(const __half2*)(vp + i * 32);
            rv[i][1] = *(const __half2*)(vp + i * 32 + 2);
        }
    }

    for (int kt = 0; kt < 256; kt += 32) {
        #pragma unroll
        for (int i = 0; i < 4; i++) {
            As[lr + i * 32][lc + 0] = ra[i].x;
            As[lr + i * 32][lc + 1] = ra[i].y;
            As[lr + i * 32][lc + 2] = ra[i].z;
            As[lr + i * 32][lc + 3] = ra[i].w;
            float2 v0 = __half22float2(rv[i][0]);
            float2 v1 = __half22float2(rv[i][1]);
            Bs[lr][lc + i * 32 + 0] = v0.x;
            Bs[lr][lc + i * 32 + 1] = v0.y;
            Bs[lr][lc + i * 32 + 2] = v1.x;
            Bs[lr][lc + i * 32 + 3] = v1.y;
        }
        __syncthreads();
        if (kt + 32 < 256) {
            #pragma unroll
            for (int i = 0; i < 4; i++)
                ra[i] = *(const float4*)(Ab + (size_t)(i * 32) * 256 + (kt + 32));
            const int jj = kt + 32 + lr;
            const int vrow = (jj < 128) ? (b * SEQ + prevblk * 128 + jj)
                                        : (b * SEQ + w * 128 + jj - 128);
            const __half* vp = qkv + (size_t)vrow * QKVN + 4096 + nb + lc;
            #pragma unroll
            for (int i = 0; i < 4; i++) {
                rv[i][0] = *(const __half2*)(vp + i * 32);
                rv[i][1] = *(const __half2*)(vp + i * 32 + 2);
            }
        }
        #pragma unroll
        for (int ks = 0; ks < 4; ks++) {
            const int k0 = ks * 8;
            float a[2][4], bb[8][2];
            #pragma unroll
            for (int mf = 0; mf < 2; mf++) {
                const int r = wm + mf * 16 + g;
                a[mf][0] = As[r][k0 + tg];
                a[mf][1] = As[r + 8][k0 + tg];
                a[mf][2] = As[r][k0 + tg + 4];
                a[mf][3] = As[r + 8][k0 + tg + 4];
            }
            #pragma unroll
            for (int nf = 0; nf < 8; nf++) {
                const int n = wn + nf * 8 + g;
                bb[nf][0] = Bs[k0 + tg][n];
                bb[nf][1] = Bs[k0 + tg + 4][n];
            }
            #pragma unroll
            for (int mf = 0; mf < 2; mf++)
                #pragma unroll
                for (int nf = 0; nf < 8; nf++)
                    mma_tf32(acc[mf][nf][0], acc[mf][nf][1], acc[mf][nf][2], acc[mf][nf][3],
                             a[mf][0], a[mf][1], a[mf][2], a[mf][3],
                             bb[nf][0], bb[nf][1]);
        }
        __syncthreads();
    }

    #pragma unroll
    for (int mf = 0; mf < 2; mf++) {
        #pragma unroll
        for (int nf = 0; nf < 8; nf++) {
            const int row = b * SEQ + w * 128 + wm + mf * 16 + g;
            const int col = nb + wn + nf * 8 + (tg << 1);
            *(__half2*)(ao + (size_t)row * DIM + col) =
                __floats2half2_rn(acc[mf][nf][0], acc[mf][nf][1]);
            *(__half2*)(ao + (size_t)(row + 8) * DIM + col) =
                __floats2half2_rn(acc[mf][nf][2], acc[mf][nf][3]);
        }
    }
}

// ---------------------------------------------------------------------------
// elementwise fp32 -> fp16
// ---------------------------------------------------------------------------
__global__ __launch_bounds__(256)
void to_half_kernel(const float4* __restrict__ in, __half2* __restrict__ out, int n4) {
    int i = blockIdx.x * blockDim.x + threadIdx.x;
    if (i < n4) {
        float4 v = in[i];
        out[2 * i + 0] = __floats2half2_rn(v.x, v.y);
        out[2 * i + 1] = __floats2half2_rn(v.z, v.w);
    }
}

// ---------------------------------------------------------------------------
// launch
// ---------------------------------------------------------------------------
extern "C" void kernel_launch(void* const* d_in, const int* in_sizes, int n_in,
                              void* d_out, int out_size) {
    const float* x      = (const float*)d_in[0];
    const float* w_attn = (const float*)d_in[1];
    const float* w_o    = (const float*)d_in[2];
    float* out = (float*)d_out;

    __half *qkv, *ao, *xh, *wah, *woh;
    float *attn;
    cudaGetSymbolAddress((void**)&qkv, g_qkv);
    cudaGetSymbolAddress((void**)&attn, g_attn);
    cudaGetSymbolAddress((void**)&ao, g_ao);
    cudaGetSymbolAddress((void**)&xh, g_xh);
    cudaGetSymbolAddress((void**)&wah, g_wah);
    cudaGetSymbolAddress((void**)&woh, g_woh);

    cudaFuncSetAttribute(gemm_h_kernel,
                         cudaFuncAttributeMaxDynamicSharedMemorySize, GA_SMEM);
    cudaFuncSetAttribute(attn_sim_kernel,
                         cudaFuncAttributeMaxDynamicSharedMemorySize, SI_SMEM);

    // convert inputs to fp16
    {
        int n4;
        n4 = ROWS * DIM / 4;
        to_half_kernel<<<(n4 + 255) / 256, 256>>>((const float4*)x, (__half2*)xh, n4);
        n4 = QKVN * DIM / 4;
        to_half_kernel<<<(n4 + 255) / 256, 256>>>((const float4*)w_attn, (__half2*)wah, n4);
        n4 = DIM * DIM / 4;
        to_half_kernel<<<(n4 + 255) / 256, 256>>>((const float4*)w_o, (__half2*)woh, n4);
    }

    // qkv = x @ w_attn^T : [16384, 6144] fp16 out
    gemm_h_kernel<<<dim3(QKVN / 256, ROWS / 128), 256, GA_SMEM>>>(
        xh, wah, qkv, DIM, DIM, QKVN, DIM, 1);
    // sim -> masked relu^2 attn weights
    attn_sim_kernel<<<dim3(2, NBLK, BATCH), 256, SI_SMEM>>>(qkv, attn);
    // out_blk = attn @ V2 -> ao fp16
    attn_pv_kernel<<<dim3(DIM / 128, NBLK, BATCH), 256>>>(qkv, attn, ao);
    // final = ao @ w_o^T -> fp32 out
    gemm_h_kernel<<<dim3(DIM / 256, ROWS / 128), 256, GA_SMEM>>>(
        ao, woh, out, DIM, DIM, DIM, DIM, 0);
}

// round 8
// speedup vs baseline: 1.0805x; 1.0805x over previous
#include <cuda_runtime.h>
#include <cuda_fp16.h>
#include <cstdint>

// Problem constants: B=2, T=8192, D=2048, W=128
#define BATCH 2
#define SEQ   8192
#define DIM   2048
#define WIN   128
#define NBLK  64
#define ROWS  16384
#define QKVN  6144

// Scratch (device globals: the sanctioned alloc-free workaround)
__device__ __half g_qkv[(size_t)ROWS * QKVN];
__device__ float  g_attn[(size_t)BATCH * NBLK * 128 * 256];
__device__ __half g_ao[(size_t)ROWS * DIM];
__device__ __half g_xh[(size_t)ROWS * DIM];
__device__ __half g_wah[(size_t)QKVN * DIM];
__device__ __half g_woh[(size_t)DIM * DIM];

// ---------------------------------------------------------------------------
// helpers
// ---------------------------------------------------------------------------
__device__ __forceinline__ uint32_t smem_u32(const void* p) {
    uint32_t a;
    asm("{ .reg .u64 t; cvta.to.shared.u64 t, %1; cvt.u32.u64 %0, t; }" : "=r"(a) : "l"(p));
    return a;
}
__device__ __forceinline__ float cvt_tf32(float x) {
    uint32_t u;
    asm("cvt.rna.tf32.f32 %0, %1;" : "=r"(u) : "f"(x));
    return __uint_as_float(u);
}

__device__ __forceinline__ void mma_f16(float& d0, float& d1, float& d2, float& d3,
                                        uint32_t a0, uint32_t a1, uint32_t a2, uint32_t a3,
                                        uint32_t b0, uint32_t b1) {
    asm volatile(
        "mma.sync.aligned.m16n8k16.row.col.f32.f16.f16.f32 "
        "{%0,%1,%2,%3}, {%4,%5,%6,%7}, {%8,%9}, {%0,%1,%2,%3};\n"
        : "+f"(d0), "+f"(d1), "+f"(d2), "+f"(d3)
        : "r"(a0), "r"(a1), "r"(a2), "r"(a3), "r"(b0), "r"(b1));
}
__device__ __forceinline__ void mma_tf32(float& d0, float& d1, float& d2, float& d3,
                                         float a0, float a1, float a2, float a3,
                                         float b0, float b1) {
    asm volatile(
        "mma.sync.aligned.m16n8k8.row.col.f32.tf32.tf32.f32 "
        "{%0,%1,%2,%3}, {%4,%5,%6,%7}, {%8,%9}, {%0,%1,%2,%3};\n"
        : "+f"(d0), "+f"(d1), "+f"(d2), "+f"(d3)
        : "r"(__float_as_uint(a0)), "r"(__float_as_uint(a1)),
          "r"(__float_as_uint(a2)), "r"(__float_as_uint(a3)),
          "r"(__float_as_uint(b0)), "r"(__float_as_uint(b1)));
}

#define LDSM_X4(r0, r1, r2, r3, addr)                                          \
    asm volatile("ldmatrix.sync.aligned.m8n8.x4.shared.b16 {%0,%1,%2,%3}, [%4];" \
                 : "=r"(r0), "=r"(r1), "=r"(r2), "=r"(r3) : "r"(addr))

#define CP_ASYNC16(dst, src)                                                   \
    asm volatile("cp.async.cg.shared.global [%0], [%1], 16;"                   \
                 :: "r"(dst), "l"(src) : "memory")
#define CP_COMMIT() asm volatile("cp.async.commit_group;" ::: "memory")
#define CP_WAIT1()  asm volatile("cp.async.wait_group 1;" ::: "memory")

// ---------------------------------------------------------------------------
// Round-8 GEMM geometry: CTA tile 64(M) x 128(N), K-tile 64 halves.
// Row = 64 halves + 8 pad = 144B. A: 64x144, B: 128x144 per stage, 2 stages.
// 128 threads (4 warps, warp tile 32x64), 4 CTAs/SM -> 16 decorrelated warps.
#define ROW_B     144
#define G8_MAT_A  9216                  // 64*144
#define G8_STAGE  27648                 // (64+128)*144
#define G8_SMEM   (2 * G8_STAGE)        // 55296B; x4 CTAs = 221KB <= 228KB

// sim geometry (R6): 128x128 tile, 3 stages
#define SI_MAT_B  18432
#define SI_STAGE  36864
#define SI_SMEM   (3 * SI_STAGE)

// ---------------------------------------------------------------------------
// fp16 NT GEMM: C[M,N] = A[M,K] @ B[N,K]^T. CTA 64x128, 4 warps (2M x 2N),
// warp tile 32x64, 2-stage cp.async, 4 CTAs/SM.
// ---------------------------------------------------------------------------
__global__ __launch_bounds__(128, 4)
void gemm_h_kernel(const __half* __restrict__ A, const __half* __restrict__ B,
                   void* __restrict__ Cout, int lda, int ldb, int N, int K,
                   int out_half) {
    extern __shared__ __align__(128) char smem[];
    const uint32_t smem_base = smem_u32(smem);

    const int tid  = threadIdx.x;
    const int warp = tid >> 5, lane = tid & 31;
    const int wm = (warp & 1) << 5;    // 0, 32
    const int wn = (warp >> 1) << 6;   // 0, 64
    const int g  = lane >> 2, tg = lane & 3;
    const int lr = tid >> 3;           // copy row 0..15
    const int c4 = tid & 7;            // copy 16B chunk 0..7

    const int sel = lane >> 3;
    const int i8  = lane & 7;
    uint32_t a_addr[2], b_addr[4];
    #pragma unroll
    for (int mf = 0; mf < 2; mf++) {
        const int row = wm + 16 * mf + (sel & 1) * 8 + i8;
        a_addr[mf] = smem_base + (uint32_t)row * ROW_B + (sel >> 1) * 16;
    }
    #pragma unroll
    for (int np = 0; np < 4; np++) {
        const int row = wn + np * 16 + (sel >> 1) * 8 + i8;
        b_addr[np] = smem_base + G8_MAT_A + (uint32_t)row * ROW_B + (sel & 1) * 16;
    }

    const __half* Ab = A + (size_t)(blockIdx.y * 64 + lr) * lda + c4 * 8;
    const __half* Bb = B + (size_t)(blockIdx.x * 128 + lr) * ldb + c4 * 8;
    const uint32_t dA = smem_base + (uint32_t)lr * ROW_B + c4 * 16;
    const uint32_t dB = smem_base + G8_MAT_A + (uint32_t)lr * ROW_B + c4 * 16;

    float acc[2][8][4];
    #pragma unroll
    for (int i = 0; i < 2; i++)
        #pragma unroll
        for (int j = 0; j < 8; j++)
            #pragma unroll
            for (int q = 0; q < 4; q++) acc[i][j][q] = 0.f;

    const int NT = K >> 6;

    // prologue: stages 0, 1
    #pragma unroll
    for (int s = 0; s < 2; s++) {
        const uint32_t o = (uint32_t)s * G8_STAGE;
        const __half* An = Ab + s * 64;
        const __half* Bn = Bb + s * 64;
        #pragma unroll
        for (int j = 0; j < 4; j++)
            CP_ASYNC16(dA + o + j * (16 * ROW_B), An + (size_t)(j * 16) * lda);
        #pragma unroll
        for (int j = 0; j < 8; j++)
            CP_ASYNC16(dB + o + j * (16 * ROW_B), Bn + (size_t)(j * 16) * ldb);
        CP_COMMIT();
    }

    uint32_t af[2][4], bf[4][4];

    for (int it = 0; it < NT; it++) {
        CP_WAIT1();            // stage it resident
        __syncthreads();

        const uint32_t so = (uint32_t)(it & 1) * G8_STAGE;
        #pragma unroll
        for (int ks = 0; ks < 4; ks++) {
            const uint32_t ko = so + (uint32_t)ks * 32;
            #pragma unroll
            for (int mf = 0; mf < 2; mf++)
                LDSM_X4(af[mf][0], af[mf][1], af[mf][2], af[mf][3], a_addr[mf] + ko);
            #pragma unroll
            for (int np = 0; np < 4; np++)
                LDSM_X4(bf[np][0], bf[np][1], bf[np][2], bf[np][3], b_addr[np] + ko);
            #pragma unroll
            for (int mf = 0; mf < 2; mf++)
                #pragma unroll
                for (int np = 0; np < 4; np++) {
                    mma_f16(acc[mf][2 * np + 0][0], acc[mf][2 * np + 0][1],
                            acc[mf][2 * np + 0][2], acc[mf][2 * np + 0][3],
                            af[mf][0], af[mf][1], af[mf][2], af[mf][3],
                            bf[np][0], bf[np][1]);
                    mma_f16(acc[mf][2 * np + 1][0], acc[mf][2 * np + 1][1],
                            acc[mf][2 * np + 1][2], acc[mf][2 * np + 1][3],
                            af[mf][0], af[mf][1], af[mf][2], af[mf][3],
                            bf[np][2], bf[np][3]);
                }
        }
        __syncthreads();       // all warps done reading buffer (it&1)

        if (it + 2 < NT) {
            const uint32_t o = (uint32_t)(it & 1) * G8_STAGE;
            const __half* An = Ab + (it + 2) * 64;
            const __half* Bn = Bb + (it + 2) * 64;
            #pragma unroll
            for (int j = 0; j < 4; j++)
                CP_ASYNC16(dA + o + j * (16 * ROW_B), An + (size_t)(j * 16) * lda);
            #pragma unroll
            for (int j = 0; j < 8; j++)
                CP_ASYNC16(dB + o + j * (16 * ROW_B), Bn + (size_t)(j * 16) * ldb);
        }
        CP_COMMIT();
    }

    #pragma unroll
    for (int mf = 0; mf < 2; mf++) {
        #pragma unroll
        for (int nf = 0; nf < 8; nf++) {
            const int row = blockIdx.y * 64 + wm + mf * 16 + g;
            const int col = blockIdx.x * 128 + wn + nf * 8 + (tg << 1);
            if (out_half) {
                __half* C = (__half*)Cout;
                *(__half2*)(C + (size_t)row * N + col) =
                    __floats2half2_rn(acc[mf][nf][0], acc[mf][nf][1]);
                *(__half2*)(C + (size_t)(row + 8) * N + col) =
                    __floats2half2_rn(acc[mf][nf][2], acc[mf][nf][3]);
            } else {
                float* C = (float*)Cout;
                *(float2*)(C + (size_t)row * N + col) =
                    make_float2(acc[mf][nf][0], acc[mf][nf][1]);
                *(float2*)(C + (size_t)(row + 8) * N + col) =
                    make_float2(acc[mf][nf][2], acc[mf][nf][3]);
            }
        }
    }
}

// ---------------------------------------------------------------------------
// sim kernel (fp16, R6): per (b,w,half) 128x128 QK^T, mask + 1/W + relu^2.
// ---------------------------------------------------------------------------
__global__ __launch_bounds__(256, 2)
void attn_sim_kernel(const __half* __restrict__ qkv, float* __restrict__ attnOut) {
    extern __shared__ __align__(128) char smem[];
    const uint32_t smem_base = smem_u32(smem);
    const int half_ = blockIdx.x, w = blockIdx.y, b = blockIdx.z;

    const int tid  = threadIdx.x;
    const int warp = tid >> 5, lane = tid & 31;
    const int wm = (warp & 3) << 5;
    const int wn = (warp >> 2) << 6;
    const int g  = lane >> 2, tg = lane & 3;
    const int lr = tid >> 3;
    const int c4 = tid & 7;

    const int sel = lane >> 3;
    const int i8  = lane & 7;
    uint32_t a_addr[2], b_addr[4];
    #pragma unroll
    for (int mf = 0; mf < 2; mf++) {
        const int row = wm + 16 * mf + (sel & 1) * 8 + i8;
        a_addr[mf] = smem_base + (uint32_t)row * ROW_B + (sel >> 1) * 16;
    }
    #pragma unroll
    for (int np = 0; np < 4; np++) {
        const int row = wn + np * 16 + (sel >> 1) * 8 + i8;
        b_addr[np] = smem_base + SI_MAT_B + (uint32_t)row * ROW_B + (sel & 1) * 16;
    }

    const int kblk = (half_ == 0) ? (w > 0 ? w - 1 : 0) : w;
    const __half* Ab = qkv + (size_t)(b * SEQ + w * 128 + lr) * QKVN + c4 * 8;
    const __half* Bb = qkv + (size_t)(b * SEQ + kblk * 128 + lr) * QKVN + 2048 + c4 * 8;
    const uint32_t dA = smem_base + (uint32_t)lr * ROW_B + c4 * 16;
    const uint32_t dB = smem_base + SI_MAT_B + (uint32_t)lr * ROW_B + c4 * 16;

    float acc[2][8][4];
    #pragma unroll
    for (int i = 0; i < 2; i++)
        #pragma unroll
        for (int j = 0; j < 8; j++)
            #pragma unroll
            for (int q = 0; q < 4; q++) acc[i][j][q] = 0.f;

    const int NT = DIM >> 6;

    #pragma unroll
    for (int s = 0; s < 2; s++) {
        const uint32_t o = (uint32_t)s * SI_STAGE;
        const __half* An = Ab + s * 64;
        const __half* Bn = Bb + s * 64;
        #pragma unroll
        for (int j = 0; j < 4; j++) {
            CP_ASYNC16(dA + o + j * (32 * ROW_B), An + (size_t)(j * 32) * QKVN);
            CP_ASYNC16(dB + o + j * (32 * ROW_B), Bn + (size_t)(j * 32) * QKVN);
        }
        CP_COMMIT();
    }

    uint32_t af[2][4], bf[4][4];
    int s_cur = 0, s_nxt = 2;

    for (int it = 0; it < NT; it++) {
        CP_WAIT1();
        __syncthreads();

        if (it + 2 < NT) {
            const uint32_t o = (uint32_t)s_nxt * SI_STAGE;
            const __half* An = Ab + (it + 2) * 64;
            const __half* Bn = Bb + (it + 2) * 64;
            #pragma unroll
            for (int j = 0; j < 4; j++) {
                CP_ASYNC16(dA + o + j * (32 * ROW_B), An + (size_t)(j * 32) * QKVN);
                CP_ASYNC16(dB + o + j * (32 * ROW_B), Bn + (size_t)(j * 32) * QKVN);
            }
        }
        CP_COMMIT();

        const uint32_t so = (uint32_t)s_cur * SI_STAGE;
        #pragma unroll
        for (int ks = 0; ks < 4; ks++) {
            const uint32_t ko = so + (uint32_t)ks * 32;
            #pragma unroll
            for (int mf = 0; mf < 2; mf++)
                LDSM_X4(af[mf][0], af[mf][1], af[mf][2], af[mf][3], a_addr[mf] + ko);
            #pragma unroll
            for (int np = 0; np < 4; np++)
                LDSM_X4(bf[np][0], bf[np][1], bf[np][2], bf[np][3], b_addr[np] + ko);
            #pragma unroll
            for (int mf = 0; mf < 2; mf++)
                #pragma unroll
                for (int np = 0; np < 4; np++) {
                    mma_f16(acc[mf][2 * np + 0][0], acc[mf][2 * np + 0][1],
                            acc[mf][2 * np + 0][2], acc[mf][2 * np + 0][3],
                            af[mf][0], af[mf][1], af[mf][2], af[mf][3],
                            bf[np][0], bf[np][1]);
                    mma_f16(acc[mf][2 * np + 1][0], acc[mf][2 * np + 1][1],
                            acc[mf][2 * np + 1][2], acc[mf][2 * np + 1][3],
                            af[mf][0], af[mf][1], af[mf][2], af[mf][3],
                            bf[np][2], bf[np][3]);
                }
        }
        s_cur = (s_cur == 2) ? 0 : s_cur + 1;
        s_nxt = (s_nxt == 2) ? 0 : s_nxt + 1;
    }

    const bool halfvalid = (half_ == 1) || (w > 0);
    const float inv_w = 1.0f / (float)WIN;
    float* Cb = attnOut + ((size_t)(b * NBLK + w) * 128) * 256 + half_ * 128;

    #pragma unroll
    for (int mf = 0; mf < 2; mf++) {
        #pragma unroll
        for (int nf = 0; nf < 8; nf++) {
            const int qi0 = wm + mf * 16 + g;
            const int kj  = wn + nf * 8 + (tg << 1);
            #pragma unroll
            for (int rr = 0; rr < 2; rr++) {
                const int qi = qi0 + rr * 8;
                float s0 = acc[mf][nf][rr * 2 + 0] * inv_w;
                float s1 = acc[mf][nf][rr * 2 + 1] * inv_w;
                bool k0 = halfvalid && ((half_ == 0) ? (qi <= kj)     : (qi >= kj));
                bool k1 = halfvalid && ((half_ == 0) ? (qi <= kj + 1) : (qi >= kj + 1));
                float r0 = k0 ? fmaxf(s0, 0.f) : 0.f;
                float r1 = k1 ? fmaxf(s1, 0.f) : 0.f;
                float2 v;
                v.x = cvt_tf32(r0 * r0);
                v.y = cvt_tf32(r1 * r1);
                *(float2*)(Cb + (size_t)qi * 256 + kj) = v;
            }
        }
    }
}

// ---------------------------------------------------------------------------
// PV kernel (R6): attn(f32) @ V2(fp16->f32), tf32 mma, ao fp16 out.
// ---------------------------------------------------------------------------
__global__ __launch_bounds__(256, 1)
void attn_pv_kernel(const __half* __restrict__ qkv, const float* __restrict__ attn,
                    __half* __restrict__ ao) {
    const int nb = blockIdx.x * 128, w = blockIdx.y, b = blockIdx.z;
    __shared__ float As[128][36];
    __shared__ float Bs[32][136];

    const int tid  = threadIdx.x;
    const int warp = tid >> 5, lane = tid & 31;
    const int wm = (warp & 3) << 5;
    const int wn = (warp >> 2) << 6;
    const int g  = lane >> 2, tg = lane & 3;
    const int lr = tid >> 3;
    const int lc = (tid & 7) << 2;

    const int prevblk = (w > 0) ? w - 1 : 0;
    const float* Ab = attn + ((size_t)(b * NBLK + w) * 128 + lr) * 256 + lc;

    float acc[2][8][4];
    #pragma unroll
    for (int i = 0; i < 2; i++)
        #pragma unroll
        for (int j = 0; j < 8; j++)
            #pragma unroll
            for (int q = 0; q < 4; q++) acc[i][j][q] = 0.f;

    float4 ra[4];
    __half2 rv[4][2];
    {
        #pragma unroll
        for (int i = 0; i < 4; i++)
            ra[i] = *(const float4*)(Ab + (size_t)(i * 32) * 256);
        const int jj = lr;
        const int vrow = (jj < 128) ? (b * SEQ + prevblk * 128 + jj)
                                    : (b * SEQ + w * 128 + jj - 128);
        const __half* vp = qkv + (size_t)vrow * QKVN + 4096 + nb + lc;
        #pragma unroll
        for (int i = 0; i < 4; i++) {
            rv[i][0] = *(const __half2*)(vp + i * 32);
            rv[i][1] = *(const __half2*)(vp + i * 32 + 2);
        }
    }

    for (int kt = 0; kt < 256; kt += 32) {
        #pragma unroll
        for (int i = 0; i < 4; i++) {
            As[lr + i * 32][lc + 0] = ra[i].x;
            As[lr + i * 32][lc + 1] = ra[i].y;
            As[lr + i * 32][lc + 2] = ra[i].z;
            As[lr + i * 32][lc + 3] = ra[i].w;
            float2 v0 = __half22float2(rv[i][0]);
            float2 v1 = __half22float2(rv[i][1]);
            Bs[lr][lc + i * 32 + 0] = v0.x;
            Bs[lr][lc + i * 32 + 1] = v0.y;
            Bs[lr][lc + i * 32 + 2] = v1.x;
            Bs[lr][lc + i * 32 + 3] = v1.y;
        }
        __syncthreads();
        if (kt + 32 < 256) {
            #pragma unroll
            for (int i = 0; i < 4; i++)
                ra[i] = *(const float4*)(Ab + (size_t)(i * 32) * 256 + (kt + 32));
            const int jj = kt + 32 + lr;
            const int vrow = (jj < 128) ? (b * SEQ + prevblk * 128 + jj)
                                        : (b * SEQ + w * 128 + jj - 128);
            const __half* vp = qkv + (size_t)vrow * QKVN + 4096 + nb + lc;
            #pragma unroll
            for (int i = 0; i < 4; i++) {
                rv[i][0] = *(const __half2*)(vp + i * 32);
                rv[i][1] = *(const __half2*)(vp + i * 32 + 2);
            }
        }
        #pragma unroll
        for (int ks = 0; ks < 4; ks++) {
            const int k0 = ks * 8;
            float a[2][4], bb[8][2];
            #pragma unroll
            for (int mf = 0; mf < 2; mf++) {
                const int r = wm + mf * 16 + g;
                a[mf][0] = As[r][k0 + tg];
                a[mf][1] = As[r + 8][k0 + tg];
                a[mf][2] = As[r][k0 + tg + 4];
                a[mf][3] = As[r + 8][k0 + tg + 4];
            }
            #pragma unroll
            for (int nf = 0; nf < 8; nf++) {
                const int n = wn + nf * 8 + g;
                bb[nf][0] = Bs[k0 + tg][n];
                bb[nf][1] = Bs[k0 + tg + 4][n];
            }
            #pragma unroll
            for (int mf = 0; mf < 2; mf++)
                #pragma unroll
                for (int nf = 0; nf < 8; nf++)
                    mma_tf32(acc[mf][nf][0], acc[mf][nf][1], acc[mf][nf][2], acc[mf][nf][3],
                             a[mf][0], a[mf][1], a[mf][2], a[mf][3],
                             bb[nf][0], bb[nf][1]);
        }
        __syncthreads();
    }

    #pragma unroll
    for (int mf = 0; mf < 2; mf++) {
        #pragma unroll
        for (int nf = 0; nf < 8; nf++) {
            const int row = b * SEQ + w * 128 + wm + mf * 16 + g;
            const int col = nb + wn + nf * 8 + (tg << 1);
            *(__half2*)(ao + (size_t)row * DIM + col) =
                __floats2half2_rn(acc[mf][nf][0], acc[mf][nf][1]);
            *(__half2*)(ao + (size_t)(row + 8) * DIM + col) =
                __floats2half2_rn(acc[mf][nf][2], acc[mf][nf][3]);
        }
    }
}

// ---------------------------------------------------------------------------
// elementwise fp32 -> fp16
// ---------------------------------------------------------------------------
__global__ __launch_bounds__(256)
void to_half_kernel(const float4* __restrict__ in, __half2* __restrict__ out, int n4) {
    int i = blockIdx.x * blockDim.x + threadIdx.x;
    if (i < n4) {
        float4 v = in[i];
        out[2 * i + 0] = __floats2half2_rn(v.x, v.y);
        out[2 * i + 1] = __floats2half2_rn(v.z, v.w);
    }
}

// ---------------------------------------------------------------------------
// launch
// ---------------------------------------------------------------------------
extern "C" void kernel_launch(void* const* d_in, const int* in_sizes, int n_in,
                              void* d_out, int out_size) {
    const float* x      = (const float*)d_in[0];
    const float* w_attn = (const float*)d_in[1];
    const float* w_o    = (const float*)d_in[2];
    float* out = (float*)d_out;

    __half *qkv, *ao, *xh, *wah, *woh;
    float *attn;
    cudaGetSymbolAddress((void**)&qkv, g_qkv);
    cudaGetSymbolAddress((void**)&attn, g_attn);
    cudaGetSymbolAddress((void**)&ao, g_ao);
    cudaGetSymbolAddress((void**)&xh, g_xh);
    cudaGetSymbolAddress((void**)&wah, g_wah);
    cudaGetSymbolAddress((void**)&woh, g_woh);

    cudaFuncSetAttribute(gemm_h_kernel,
                         cudaFuncAttributeMaxDynamicSharedMemorySize, G8_SMEM);
    cudaFuncSetAttribute(attn_sim_kernel,
                         cudaFuncAttributeMaxDynamicSharedMemorySize, SI_SMEM);

    // convert inputs to fp16
    {
        int n4;
        n4 = ROWS * DIM / 4;
        to_half_kernel<<<(n4 + 255) / 256, 256>>>((const float4*)x, (__half2*)xh, n4);
        n4 = QKVN * DIM / 4;
        to_half_kernel<<<(n4 + 255) / 256, 256>>>((const float4*)w_attn, (__half2*)wah, n4);
        n4 = DIM * DIM / 4;
        to_half_kernel<<<(n4 + 255) / 256, 256>>>((const float4*)w_o, (__half2*)woh, n4);
    }

    // qkv = x @ w_attn^T : [16384, 6144] fp16 out
    gemm_h_kernel<<<dim3(QKVN / 128, ROWS / 64), 128, G8_SMEM>>>(
        xh, wah, qkv, DIM, DIM, QKVN, DIM, 1);
    // sim -> masked relu^2 attn weights
    attn_sim_kernel<<<dim3(2, NBLK, BATCH), 256, SI_SMEM>>>(qkv, attn);
    // out_blk = attn @ V2 -> ao fp16
    attn_pv_kernel<<<dim3(DIM / 128, NBLK, BATCH), 256>>>(qkv, attn, ao);
    // final = ao @ w_o^T -> fp32 out
    gemm_h_kernel<<<dim3(DIM / 128, ROWS / 64), 128, G8_SMEM>>>(
        ao, woh, out, DIM, DIM, DIM, DIM, 0);
}

// round 9
// speedup vs baseline: 1.1348x; 1.0503x over previous
#include <cuda_runtime.h>
#include <cuda_fp16.h>
#include <cstdint>

// Problem constants: B=2, T=8192, D=2048, W=128
#define BATCH 2
#define SEQ   8192
#define DIM   2048
#define WIN   128
#define NBLK  64
#define ROWS  16384
#define QKVN  6144

// Scratch (device globals: the sanctioned alloc-free workaround)
__device__ __half g_qkv[(size_t)ROWS * QKVN];
__device__ __half g_attn[(size_t)BATCH * NBLK * 128 * 256];   // fp16 attn weights
__device__ __half g_ao[(size_t)ROWS * DIM];
__device__ __half g_xh[(size_t)ROWS * DIM];
__device__ __half g_wah[(size_t)QKVN * DIM];
__device__ __half g_woh[(size_t)DIM * DIM];

// ---------------------------------------------------------------------------
// helpers
// ---------------------------------------------------------------------------
__device__ __forceinline__ uint32_t smem_u32(const void* p) {
    uint32_t a;
    asm("{ .reg .u64 t; cvta.to.shared.u64 t, %1; cvt.u32.u64 %0, t; }" : "=r"(a) : "l"(p));
    return a;
}

__device__ __forceinline__ void mma_f16(float& d0, float& d1, float& d2, float& d3,
                                        uint32_t a0, uint32_t a1, uint32_t a2, uint32_t a3,
                                        uint32_t b0, uint32_t b1) {
    asm volatile(
        "mma.sync.aligned.m16n8k16.row.col.f32.f16.f16.f32 "
        "{%0,%1,%2,%3}, {%4,%5,%6,%7}, {%8,%9}, {%0,%1,%2,%3};\n"
        : "+f"(d0), "+f"(d1), "+f"(d2), "+f"(d3)
        : "r"(a0), "r"(a1), "r"(a2), "r"(a3), "r"(b0), "r"(b1));
}

#define LDSM_X4(r0, r1, r2, r3, addr)                                          \
    asm volatile("ldmatrix.sync.aligned.m8n8.x4.shared.b16 {%0,%1,%2,%3}, [%4];" \
                 : "=r"(r0), "=r"(r1), "=r"(r2), "=r"(r3) : "r"(addr))
#define LDSM_X4T(r0, r1, r2, r3, addr)                                         \
    asm volatile("ldmatrix.sync.aligned.m8n8.x4.trans.shared.b16 {%0,%1,%2,%3}, [%4];" \
                 : "=r"(r0), "=r"(r1), "=r"(r2), "=r"(r3) : "r"(addr))

#define CP_ASYNC16(dst, src)                                                   \
    asm volatile("cp.async.cg.shared.global [%0], [%1], 16;"                   \
                 :: "r"(dst), "l"(src) : "memory")
#define CP_COMMIT() asm volatile("cp.async.commit_group;" ::: "memory")
#define CP_WAIT1()  asm volatile("cp.async.wait_group 1;" ::: "memory")

// ---------------------------------------------------------------------------
// GEMM geometry (R8, proven): CTA 64x128, K-tile 64, 2 stages, 4 CTAs/SM.
#define ROW_B     144
#define G8_MAT_A  9216
#define G8_STAGE  27648
#define G8_SMEM   (2 * G8_STAGE)

// sim geometry: 128x128 tile, 3 stages
#define SI_MAT_B  18432
#define SI_STAGE  36864
#define SI_SMEM   (3 * SI_STAGE)

// PV geometry: CTA 128(M) x 128(N), K-tile 64.
// A (attn): 128 rows x 144B. B (V2): 64 k-rows x 272B (128 halves + 8 pad).
#define PV_ROWV_B 272
#define PV_MAT_A  18432                  // 128*144
#define PV_MAT_B  17408                  // 64*272
#define PV_STAGE  (PV_MAT_A + PV_MAT_B)  // 35840
#define PV_SMEM   (2 * PV_STAGE)         // 71680; x2 CTAs = 143KB

// ---------------------------------------------------------------------------
// fp16 NT GEMM (R8, unchanged): CTA 64x128, 4 warps, 2-stage, 4 CTAs/SM.
// ---------------------------------------------------------------------------
__global__ __launch_bounds__(128, 4)
void gemm_h_kernel(const __half* __restrict__ A, const __half* __restrict__ B,
                   void* __restrict__ Cout, int lda, int ldb, int N, int K,
                   int out_half) {
    extern __shared__ __align__(128) char smem[];
    const uint32_t smem_base = smem_u32(smem);

    const int tid  = threadIdx.x;
    const int warp = tid >> 5, lane = tid & 31;
    const int wm = (warp & 1) << 5;
    const int wn = (warp >> 1) << 6;
    const int g  = lane >> 2, tg = lane & 3;
    const int lr = tid >> 3;
    const int c4 = tid & 7;

    const int sel = lane >> 3;
    const int i8  = lane & 7;
    uint32_t a_addr[2], b_addr[4];
    #pragma unroll
    for (int mf = 0; mf < 2; mf++) {
        const int row = wm + 16 * mf + (sel & 1) * 8 + i8;
        a_addr[mf] = smem_base + (uint32_t)row * ROW_B + (sel >> 1) * 16;
    }
    #pragma unroll
    for (int np = 0; np < 4; np++) {
        const int row = wn + np * 16 + (sel >> 1) * 8 + i8;
        b_addr[np] = smem_base + G8_MAT_A + (uint32_t)row * ROW_B + (sel & 1) * 16;
    }

    const __half* Ab = A + (size_t)(blockIdx.y * 64 + lr) * lda + c4 * 8;
    const __half* Bb = B + (size_t)(blockIdx.x * 128 + lr) * ldb + c4 * 8;
    const uint32_t dA = smem_base + (uint32_t)lr * ROW_B + c4 * 16;
    const uint32_t dB = smem_base + G8_MAT_A + (uint32_t)lr * ROW_B + c4 * 16;

    float acc[2][8][4];
    #pragma unroll
    for (int i = 0; i < 2; i++)
        #pragma unroll
        for (int j = 0; j < 8; j++)
            #pragma unroll
            for (int q = 0; q < 4; q++) acc[i][j][q] = 0.f;

    const int NT = K >> 6;

    #pragma unroll
    for (int s = 0; s < 2; s++) {
        const uint32_t o = (uint32_t)s * G8_STAGE;
        const __half* An = Ab + s * 64;
        const __half* Bn = Bb + s * 64;
        #pragma unroll
        for (int j = 0; j < 4; j++)
            CP_ASYNC16(dA + o + j * (16 * ROW_B), An + (size_t)(j * 16) * lda);
        #pragma unroll
        for (int j = 0; j < 8; j++)
            CP_ASYNC16(dB + o + j * (16 * ROW_B), Bn + (size_t)(j * 16) * ldb);
        CP_COMMIT();
    }

    uint32_t af[2][4], bf[4][4];

    for (int it = 0; it < NT; it++) {
        CP_WAIT1();
        __syncthreads();

        const uint32_t so = (uint32_t)(it & 1) * G8_STAGE;
        #pragma unroll
        for (int ks = 0; ks < 4; ks++) {
            const uint32_t ko = so + (uint32_t)ks * 32;
            #pragma unroll
            for (int mf = 0; mf < 2; mf++)
                LDSM_X4(af[mf][0], af[mf][1], af[mf][2], af[mf][3], a_addr[mf] + ko);
            #pragma unroll
            for (int np = 0; np < 4; np++)
                LDSM_X4(bf[np][0], bf[np][1], bf[np][2], bf[np][3], b_addr[np] + ko);
            #pragma unroll
            for (int mf = 0; mf < 2; mf++)
                #pragma unroll
                for (int np = 0; np < 4; np++) {
                    mma_f16(acc[mf][2 * np + 0][0], acc[mf][2 * np + 0][1],
                            acc[mf][2 * np + 0][2], acc[mf][2 * np + 0][3],
                            af[mf][0], af[mf][1], af[mf][2], af[mf][3],
                            bf[np][0], bf[np][1]);
                    mma_f16(acc[mf][2 * np + 1][0], acc[mf][2 * np + 1][1],
                            acc[mf][2 * np + 1][2], acc[mf][2 * np + 1][3],
                            af[mf][0], af[mf][1], af[mf][2], af[mf][3],
                            bf[np][2], bf[np][3]);
                }
        }
        __syncthreads();

        if (it + 2 < NT) {
            const uint32_t o = (uint32_t)(it & 1) * G8_STAGE;
            const __half* An = Ab + (it + 2) * 64;
            const __half* Bn = Bb + (it + 2) * 64;
            #pragma unroll
            for (int j = 0; j < 4; j++)
                CP_ASYNC16(dA + o + j * (16 * ROW_B), An + (size_t)(j * 16) * lda);
            #pragma unroll
            for (int j = 0; j < 8; j++)
                CP_ASYNC16(dB + o + j * (16 * ROW_B), Bn + (size_t)(j * 16) * ldb);
        }
        CP_COMMIT();
    }

    #pragma unroll
    for (int mf = 0; mf < 2; mf++) {
        #pragma unroll
        for (int nf = 0; nf < 8; nf++) {
            const int row = blockIdx.y * 64 + wm + mf * 16 + g;
            const int col = blockIdx.x * 128 + wn + nf * 8 + (tg << 1);
            if (out_half) {
                __half* C = (__half*)Cout;
                *(__half2*)(C + (size_t)row * N + col) =
                    __floats2half2_rn(acc[mf][nf][0], acc[mf][nf][1]);
                *(__half2*)(C + (size_t)(row + 8) * N + col) =
                    __floats2half2_rn(acc[mf][nf][2], acc[mf][nf][3]);
            } else {
                float* C = (float*)Cout;
                *(float2*)(C + (size_t)row * N + col) =
                    make_float2(acc[mf][nf][0], acc[mf][nf][1]);
                *(float2*)(C + (size_t)(row + 8) * N + col) =
                    make_float2(acc[mf][nf][2], acc[mf][nf][3]);
            }
        }
    }
}

// ---------------------------------------------------------------------------
// sim kernel: per (b,w,half) 128x128 QK^T, mask + 1/W + relu^2 -> fp16 attn.
// ---------------------------------------------------------------------------
__global__ __launch_bounds__(256, 2)
void attn_sim_kernel(const __half* __restrict__ qkv, __half* __restrict__ attnOut) {
    extern __shared__ __align__(128) char smem[];
    const uint32_t smem_base = smem_u32(smem);
    const int half_ = blockIdx.x, w = blockIdx.y, b = blockIdx.z;

    const int tid  = threadIdx.x;
    const int warp = tid >> 5, lane = tid & 31;
    const int wm = (warp & 3) << 5;
    const int wn = (warp >> 2) << 6;
    const int g  = lane >> 2, tg = lane & 3;
    const int lr = tid >> 3;
    const int c4 = tid & 7;

    const int sel = lane >> 3;
    const int i8  = lane & 7;
    uint32_t a_addr[2], b_addr[4];
    #pragma unroll
    for (int mf = 0; mf < 2; mf++) {
        const int row = wm + 16 * mf + (sel & 1) * 8 + i8;
        a_addr[mf] = smem_base + (uint32_t)row * ROW_B + (sel >> 1) * 16;
    }
    #pragma unroll
    for (int np = 0; np < 4; np++) {
        const int row = wn + np * 16 + (sel >> 1) * 8 + i8;
        b_addr[np] = smem_base + SI_MAT_B + (uint32_t)row * ROW_B + (sel & 1) * 16;
    }

    const int kblk = (half_ == 0) ? (w > 0 ? w - 1 : 0) : w;
    const __half* Ab = qkv + (size_t)(b * SEQ + w * 128 + lr) * QKVN + c4 * 8;
    const __half* Bb = qkv + (size_t)(b * SEQ + kblk * 128 + lr) * QKVN + 2048 + c4 * 8;
    const uint32_t dA = smem_base + (uint32_t)lr * ROW_B + c4 * 16;
    const uint32_t dB = smem_base + SI_MAT_B + (uint32_t)lr * ROW_B + c4 * 16;

    float acc[2][8][4];
    #pragma unroll
    for (int i = 0; i < 2; i++)
        #pragma unroll
        for (int j = 0; j < 8; j++)
            #pragma unroll
            for (int q = 0; q < 4; q++) acc[i][j][q] = 0.f;

    const int NT = DIM >> 6;

    #pragma unroll
    for (int s = 0; s < 2; s++) {
        const uint32_t o = (uint32_t)s * SI_STAGE;
        const __half* An = Ab + s * 64;
        const __half* Bn = Bb + s * 64;
        #pragma unroll
        for (int j = 0; j < 4; j++) {
            CP_ASYNC16(dA + o + j * (32 * ROW_B), An + (size_t)(j * 32) * QKVN);
            CP_ASYNC16(dB + o + j * (32 * ROW_B), Bn + (size_t)(j * 32) * QKVN);
        }
        CP_COMMIT();
    }

    uint32_t af[2][4], bf[4][4];
    int s_cur = 0, s_nxt = 2;

    for (int it = 0; it < NT; it++) {
        CP_WAIT1();
        __syncthreads();

        if (it + 2 < NT) {
            const uint32_t o = (uint32_t)s_nxt * SI_STAGE;
            const __half* An = Ab + (it + 2) * 64;
            const __half* Bn = Bb + (it + 2) * 64;
            #pragma unroll
            for (int j = 0; j < 4; j++) {
                CP_ASYNC16(dA + o + j * (32 * ROW_B), An + (size_t)(j * 32) * QKVN);
                CP_ASYNC16(dB + o + j * (32 * ROW_B), Bn + (size_t)(j * 32) * QKVN);
            }
        }
        CP_COMMIT();

        const uint32_t so = (uint32_t)s_cur * SI_STAGE;
        #pragma unroll
        for (int ks = 0; ks < 4; ks++) {
            const uint32_t ko = so + (uint32_t)ks * 32;
            #pragma unroll
            for (int mf = 0; mf < 2; mf++)
                LDSM_X4(af[mf][0], af[mf][1], af[mf][2], af[mf][3], a_addr[mf] + ko);
            #pragma unroll
            for (int np = 0; np < 4; np++)
                LDSM_X4(bf[np][0], bf[np][1], bf[np][2], bf[np][3], b_addr[np] + ko);
            #pragma unroll
            for (int mf = 0; mf < 2; mf++)
                #pragma unroll
                for (int np = 0; np < 4; np++) {
                    mma_f16(acc[mf][2 * np + 0][0], acc[mf][2 * np + 0][1],
                            acc[mf][2 * np + 0][2], acc[mf][2 * np + 0][3],
                            af[mf][0], af[mf][1], af[mf][2], af[mf][3],
                            bf[np][0], bf[np][1]);
                    mma_f16(acc[mf][2 * np + 1][0], acc[mf][2 * np + 1][1],
                            acc[mf][2 * np + 1][2], acc[mf][2 * np + 1][3],
                            af[mf][0], af[mf][1], af[mf][2], af[mf][3],
                            bf[np][2], bf[np][3]);
                }
        }
        s_cur = (s_cur == 2) ? 0 : s_cur + 1;
        s_nxt = (s_nxt == 2) ? 0 : s_nxt + 1;
    }

    const bool halfvalid = (half_ == 1) || (w > 0);
    const float inv_w = 1.0f / (float)WIN;
    __half* Cb = attnOut + ((size_t)(b * NBLK + w) * 128) * 256 + half_ * 128;

    #pragma unroll
    for (int mf = 0; mf < 2; mf++) {
        #pragma unroll
        for (int nf = 0; nf < 8; nf++) {
            const int qi0 = wm + mf * 16 + g;
            const int kj  = wn + nf * 8 + (tg << 1);
            #pragma unroll
            for (int rr = 0; rr < 2; rr++) {
                const int qi = qi0 + rr * 8;
                float s0 = acc[mf][nf][rr * 2 + 0] * inv_w;
                float s1 = acc[mf][nf][rr * 2 + 1] * inv_w;
                bool k0 = halfvalid && ((half_ == 0) ? (qi <= kj)     : (qi >= kj));
                bool k1 = halfvalid && ((half_ == 0) ? (qi <= kj + 1) : (qi >= kj + 1));
                float r0 = k0 ? fmaxf(s0, 0.f) : 0.f;
                float r1 = k1 ? fmaxf(s1, 0.f) : 0.f;
                *(__half2*)(Cb + (size_t)qi * 256 + kj) =
                    __floats2half2_rn(r0 * r0, r1 * r1);
            }
        }
    }
}

// ---------------------------------------------------------------------------
// PV kernel (fp16): out_blk[128, nb..nb+128] = attn[128,256] @ V2[256, ...].
// A = attn (k-contiguous fp16, normal ldmatrix). B = V2 stored [k][n] in smem,
// loaded with ldmatrix.trans (equivalent fragments to the proven [n][k] path).
// CTA 128x128, 8 warps (4M x 2N), 2-stage cp.async, 2 CTAs/SM.
// ---------------------------------------------------------------------------
__global__ __launch_bounds__(256, 2)
void attn_pv_kernel(const __half* __restrict__ qkv, const __half* __restrict__ attn,
                    __half* __restrict__ ao) {
    extern __shared__ __align__(128) char smem[];
    const uint32_t smem_base = smem_u32(smem);
    const int nb = blockIdx.x * 128, w = blockIdx.y, b = blockIdx.z;

    const int tid  = threadIdx.x;
    const int warp = tid >> 5, lane = tid & 31;
    const int wm = (warp & 3) << 5;   // 4 M-warps x 32
    const int wn = (warp >> 2) << 6;  // 2 N-warps x 64
    const int g  = lane >> 2, tg = lane & 3;
    const int lr = tid >> 3;          // A copy row 0..31
    const int c4 = tid & 7;           // A copy chunk
    const int vrow = tid >> 2;        // B copy row 0..63
    const int vc   = (tid & 3) * 4;   // B copy chunk base (of 16)

    const int sel = lane >> 3;
    const int i8  = lane & 7;
    // A fragment addresses (normal ldmatrix, rows = M)
    uint32_t a_addr[2];
    #pragma unroll
    for (int mf = 0; mf < 2; mf++) {
        const int row = wm + 16 * mf + (sel & 1) * 8 + i8;
        a_addr[mf] = smem_base + (uint32_t)row * ROW_B + (sel >> 1) * 16;
    }
    // B fragment addresses (trans ldmatrix, rows = k, cols = n):
    // tile sel&1 -> k-group (0/8), sel>>1 -> n-group (0/8)
    uint32_t b_addr[4];
    #pragma unroll
    for (int np = 0; np < 4; np++) {
        b_addr[np] = smem_base + PV_MAT_A
                   + (uint32_t)((sel & 1) * 8 + i8) * PV_ROWV_B
                   + (uint32_t)(wn + 16 * np + (sel >> 1) * 8) * 2;
    }

    const int prevblk = (w > 0) ? w - 1 : 0;
    const __half* Ag = attn + ((size_t)(b * NBLK + w) * 128 + lr) * 256 + c4 * 8;
    const uint32_t dA = smem_base + (uint32_t)lr * ROW_B + c4 * 16;
    const uint32_t dV = smem_base + PV_MAT_A + (uint32_t)vrow * PV_ROWV_B + vc * 16;

    float acc[2][8][4];
    #pragma unroll
    for (int i = 0; i < 2; i++)
        #pragma unroll
        for (int j = 0; j < 8; j++)
            #pragma unroll
            for (int q = 0; q < 4; q++) acc[i][j][q] = 0.f;

    // V row pointer for k-tile `it`: global k = it*64 + vrow
    auto vptr = [&](int it) -> const __half* {
        const int kk = it * 64 + vrow;
        const int tok = (kk < 128) ? (b * SEQ + prevblk * 128 + kk)
                                   : (b * SEQ + w * 128 + kk - 128);
        return qkv + (size_t)tok * QKVN + 4096 + nb;
    };

    // prologue: stages 0, 1
    #pragma unroll
    for (int s = 0; s < 2; s++) {
        const uint32_t o = (uint32_t)s * PV_STAGE;
        #pragma unroll
        for (int j = 0; j < 4; j++)
            CP_ASYNC16(dA + o + j * (32 * ROW_B), Ag + (size_t)(j * 32) * 256 + s * 64);
        const __half* vp = vptr(s);
        #pragma unroll
        for (int j = 0; j < 4; j++)
            CP_ASYNC16(dV + o + j * 16, vp + (vc + j) * 8);
        CP_COMMIT();
    }

    uint32_t af[2][4], bf[4][4];

    for (int it = 0; it < 4; it++) {        // K = 256 = 4 tiles of 64
        CP_WAIT1();
        __syncthreads();

        const uint32_t so = (uint32_t)(it & 1) * PV_STAGE;
        #pragma unroll
        for (int ks = 0; ks < 4; ks++) {
            const uint32_t koA = so + (uint32_t)ks * 32;
            const uint32_t koB = so + (uint32_t)ks * (16 * PV_ROWV_B);
            #pragma unroll
            for (int mf = 0; mf < 2; mf++)
                LDSM_X4(af[mf][0], af[mf][1], af[mf][2], af[mf][3], a_addr[mf] + koA);
            #pragma unroll
            for (int np = 0; np < 4; np++)
                LDSM_X4T(bf[np][0], bf[np][1], bf[np][2], bf[np][3], b_addr[np] + koB);
            #pragma unroll
            for (int mf = 0; mf < 2; mf++)
                #pragma unroll
                for (int np = 0; np < 4; np++) {
                    mma_f16(acc[mf][2 * np + 0][0], acc[mf][2 * np + 0][1],
                            acc[mf][2 * np + 0][2], acc[mf][2 * np + 0][3],
                            af[mf][0], af[mf][1], af[mf][2], af[mf][3],
                            bf[np][0], bf[np][1]);
                    mma_f16(acc[mf][2 * np + 1][0], acc[mf][2 * np + 1][1],
                            acc[mf][2 * np + 1][2], acc[mf][2 * np + 1][3],
                            af[mf][0], af[mf][1], af[mf][2], af[mf][3],
                            bf[np][2], bf[np][3]);
                }
        }
        __syncthreads();

        if (it + 2 < 4) {
            const uint32_t o = (uint32_t)(it & 1) * PV_STAGE;
            #pragma unroll
            for (int j = 0; j < 4; j++)
                CP_ASYNC16(dA + o + j * (32 * ROW_B),
                           Ag + (size_t)(j * 32) * 256 + (it + 2) * 64);
            const __half* vp = vptr(it + 2);
            #pragma unroll
            for (int j = 0; j < 4; j++)
                CP_ASYNC16(dV + o + j * 16, vp + (vc + j) * 8);
        }
        CP_COMMIT();
    }

    #pragma unroll
    for (int mf = 0; mf < 2; mf++) {
        #pragma unroll
        for (int nf = 0; nf < 8; nf++) {
            const int row = b * SEQ + w * 128 + wm + mf * 16 + g;
            const int col = nb + wn + nf * 8 + (tg << 1);
            *(__half2*)(ao + (size_t)row * DIM + col) =
                __floats2half2_rn(acc[mf][nf][0], acc[mf][nf][1]);
            *(__half2*)(ao + (size_t)(row + 8) * DIM + col) =
                __floats2half2_rn(acc[mf][nf][2], acc[mf][nf][3]);
        }
    }
}

// ---------------------------------------------------------------------------
// elementwise fp32 -> fp16
// ---------------------------------------------------------------------------
__global__ __launch_bounds__(256)
void to_half_kernel(const float4* __restrict__ in, __half2* __restrict__ out, int n4) {
    int i = blockIdx.x * blockDim.x + threadIdx.x;
    if (i < n4) {
        float4 v = in[i];
        out[2 * i + 0] = __floats2half2_rn(v.x, v.y);
        out[2 * i + 1] = __floats2half2_rn(v.z, v.w);
    }
}

// ---------------------------------------------------------------------------
// launch
// ---------------------------------------------------------------------------
extern "C" void kernel_launch(void* const* d_in, const int* in_sizes, int n_in,
                              void* d_out, int out_size) {
    const float* x      = (const float*)d_in[0];
    const float* w_attn = (const float*)d_in[1];
    const float* w_o    = (const float*)d_in[2];
    float* out = (float*)d_out;

    __half *qkv, *attn, *ao, *xh, *wah, *woh;
    cudaGetSymbolAddress((void**)&qkv, g_qkv);
    cudaGetSymbolAddress((void**)&attn, g_attn);
    cudaGetSymbolAddress((void**)&ao, g_ao);
    cudaGetSymbolAddress((void**)&xh, g_xh);
    cudaGetSymbolAddress((void**)&wah, g_wah);
    cudaGetSymbolAddress((void**)&woh, g_woh);

    cudaFuncSetAttribute(gemm_h_kernel,
                         cudaFuncAttributeMaxDynamicSharedMemorySize, G8_SMEM);
    cudaFuncSetAttribute(attn_sim_kernel,
                         cudaFuncAttributeMaxDynamicSharedMemorySize, SI_SMEM);
    cudaFuncSetAttribute(attn_pv_kernel,
                         cudaFuncAttributeMaxDynamicSharedMemorySize, PV_SMEM);

    // convert inputs to fp16
    {
        int n4;
        n4 = ROWS * DIM / 4;
        to_half_kernel<<<(n4 + 255) / 256, 256>>>((const float4*)x, (__half2*)xh, n4);
        n4 = QKVN * DIM / 4;
        to_half_kernel<<<(n4 + 255) / 256, 256>>>((const float4*)w_attn, (__half2*)wah, n4);
        n4 = DIM * DIM / 4;
        to_half_kernel<<<(n4 + 255) / 256, 256>>>((const float4*)w_o, (__half2*)woh, n4);
    }

    // qkv = x @ w_attn^T : [16384, 6144] fp16 out
    gemm_h_kernel<<<dim3(QKVN / 128, ROWS / 64), 128, G8_SMEM>>>(
        xh, wah, qkv, DIM, DIM, QKVN, DIM, 1);
    // sim -> masked relu^2 attn weights (fp16)
    attn_sim_kernel<<<dim3(2, NBLK, BATCH), 256, SI_SMEM>>>(qkv, attn);
    // out_blk = attn @ V2 -> ao fp16 (fp16 tensor path)
    attn_pv_kernel<<<dim3(DIM / 128, NBLK, BATCH), 256, PV_SMEM>>>(qkv, attn, ao);
    // final = ao @ w_o^T -> fp32 out
    gemm_h_kernel<<<dim3(DIM / 128, ROWS / 64), 128, G8_SMEM>>>(
        ao, woh, out, DIM, DIM, DIM, DIM, 0);
}